// round 1
// baseline (speedup 1.0000x reference)
#include <cuda_runtime.h>
#include <math.h>

#define HW 4096
#define WID 64

// Scratch (allocation-free: device globals)
__device__ float g_qkv1[2 * 576 * 4096];   // after 1x1 conv
__device__ float g_qkv2[2 * 576 * 4096];   // after depthwise 3x3 (+ q,k normalized in place)
__device__ float g_att [2 * 192 * 4096];   // attention output (channel = h*32+d)

// ---------------------------------------------------------------------------
// GEMM with bias: C[z] = A[M,K] @ B[z][K,N] + bias  (row-major everywhere)
// BM=64 BN=128 BK=16, 256 threads, 4x8 register tile.
// Requires M%64==0, K%16==0, N%128==0 (holds: 576/192, 192, 4096).
// ---------------------------------------------------------------------------
__global__ void gemm_bias_kernel(const float* __restrict__ A,
                                 const float* __restrict__ Bg,
                                 const float* __restrict__ bias,
                                 float* __restrict__ Cg,
                                 int M, int K, int N)
{
    __shared__ float As[16][64];
    __shared__ float Bs[16][128];

    const int bN = blockIdx.x * 128;
    const int bM = blockIdx.y * 64;
    const float* Bp = Bg + (size_t)blockIdx.z * (size_t)K * N;
    float*       Cp = Cg + (size_t)blockIdx.z * (size_t)M * N;

    const int tid  = threadIdx.x;
    const int tcol = tid & 15;    // 16 cols * TN(8) = 128
    const int trow = tid >> 4;    // 16 rows * TM(4) = 64

    float acc[4][8];
#pragma unroll
    for (int i = 0; i < 4; i++)
#pragma unroll
        for (int j = 0; j < 8; j++) acc[i][j] = 0.f;

    const int a_r = tid >> 2;         // 0..63
    const int a_c = (tid & 3) << 2;   // 0,4,8,12
    const int b_r = tid >> 4;         // 0..15
    const int b_c = (tid & 15) << 3;  // 0..120

    for (int k0 = 0; k0 < K; k0 += 16) {
        float4 av = *reinterpret_cast<const float4*>(&A[(size_t)(bM + a_r) * K + k0 + a_c]);
        As[a_c + 0][a_r] = av.x;
        As[a_c + 1][a_r] = av.y;
        As[a_c + 2][a_r] = av.z;
        As[a_c + 3][a_r] = av.w;

        const float* bsrc = Bp + (size_t)(k0 + b_r) * N + bN + b_c;
        *reinterpret_cast<float4*>(&Bs[b_r][b_c])     = *reinterpret_cast<const float4*>(bsrc);
        *reinterpret_cast<float4*>(&Bs[b_r][b_c + 4]) = *reinterpret_cast<const float4*>(bsrc + 4);
        __syncthreads();

#pragma unroll
        for (int k = 0; k < 16; k++) {
            float a4[4], b8[8];
            *reinterpret_cast<float4*>(a4)     = *reinterpret_cast<const float4*>(&As[k][trow << 2]);
            *reinterpret_cast<float4*>(b8)     = *reinterpret_cast<const float4*>(&Bs[k][tcol << 3]);
            *reinterpret_cast<float4*>(b8 + 4) = *reinterpret_cast<const float4*>(&Bs[k][(tcol << 3) + 4]);
#pragma unroll
            for (int i = 0; i < 4; i++)
#pragma unroll
                for (int j = 0; j < 8; j++)
                    acc[i][j] += a4[i] * b8[j];
        }
        __syncthreads();
    }

#pragma unroll
    for (int i = 0; i < 4; i++) {
        int gm = bM + (trow << 2) + i;
        float bv = bias[gm];
        float* dst = Cp + (size_t)gm * N + bN + (tcol << 3);
        float4 o0 = make_float4(acc[i][0] + bv, acc[i][1] + bv, acc[i][2] + bv, acc[i][3] + bv);
        float4 o1 = make_float4(acc[i][4] + bv, acc[i][5] + bv, acc[i][6] + bv, acc[i][7] + bv);
        *reinterpret_cast<float4*>(dst)     = o0;
        *reinterpret_cast<float4*>(dst + 4) = o1;
    }
}

// ---------------------------------------------------------------------------
// Depthwise 3x3 SAME conv, NCHW, 576 channels. Thread = (b, c, row, 8-col strip).
// ---------------------------------------------------------------------------
__global__ void dwconv_kernel(const float* __restrict__ in,
                              const float* __restrict__ w9,   // [576][9]
                              const float* __restrict__ bias, // [576]
                              float* __restrict__ outp)
{
    int idx = blockIdx.x * 256 + threadIdx.x;
    if (idx >= 2 * 576 * 64 * 8) return;
    const int j0 = (idx & 7) << 3;
    const int i  = (idx >> 3) & 63;
    const int bc = idx >> 9;            // b*576 + c
    const int c  = bc % 576;

    const float* src = in + (size_t)bc * HW;

    float wv[9];
#pragma unroll
    for (int t = 0; t < 9; t++) wv[t] = __ldg(&w9[c * 9 + t]);
    const float bv = __ldg(&bias[c]);

    float a[8];
#pragma unroll
    for (int j = 0; j < 8; j++) a[j] = bv;

#pragma unroll
    for (int di = 0; di < 3; di++) {
        int ii = i + di - 1;
        if (ii < 0 || ii > 63) continue;
        float r[10];
#pragma unroll
        for (int t = 0; t < 10; t++) {
            int jj = j0 - 1 + t;
            r[t] = (jj >= 0 && jj < 64) ? src[ii * WID + jj] : 0.f;
        }
#pragma unroll
        for (int dj = 0; dj < 3; dj++) {
            float wc = wv[di * 3 + dj];
#pragma unroll
            for (int j = 0; j < 8; j++) a[j] += wc * r[j + dj];
        }
    }

    float* dst = outp + (size_t)bc * HW + i * WID + j0;
    *reinterpret_cast<float4*>(dst)     = make_float4(a[0], a[1], a[2], a[3]);
    *reinterpret_cast<float4*>(dst + 4) = make_float4(a[4], a[5], a[6], a[7]);
}

// ---------------------------------------------------------------------------
// L2-normalize q and k over hd=32 (channels 0..383 of g_qkv2, grouped by 32).
// Warp handles (b, group, 32 consecutive pixels); lane = pixel. Coalesced.
// ---------------------------------------------------------------------------
__global__ void l2norm_kernel(float* __restrict__ t)
{
    const int gw   = (blockIdx.x * blockDim.x + threadIdx.x) >> 5;
    const int lane = threadIdx.x & 31;
    const int pg = gw & 127;           // 128 pixel groups of 32
    const int hq = (gw >> 7) % 12;     // 12 head-groups (6 q + 6 k)
    const int b  = (gw >> 7) / 12;

    float* base = t + (size_t)(b * 576 + hq * 32) * HW + pg * 32 + lane;
    float v[32];
    float ss = 0.f;
#pragma unroll
    for (int d = 0; d < 32; d++) {
        v[d] = base[(size_t)d * HW];
        ss += v[d] * v[d];
    }
    float sc = 1.f / fmaxf(sqrtf(ss), 1e-12f);
#pragma unroll
    for (int d = 0; d < 32; d++) base[(size_t)d * HW] = v[d] * sc;
}

// ---------------------------------------------------------------------------
// Neighborhood attention (7x7 clipped window), block = (8x8 pixel tile, head, b).
// K tile and V tile share one smem buffer (phased). Probs staged in smem.
// ---------------------------------------------------------------------------
__global__ void natten_kernel(const float* __restrict__ qkv,  // g_qkv2
                              const float* __restrict__ rpb,  // [6][13][13]
                              const float* __restrict__ temp, // [6]
                              float* __restrict__ outp)       // g_att [B,192,HW]
{
    const int h  = blockIdx.z % 6;
    const int b  = blockIdx.z / 6;
    const int i0 = blockIdx.y * 8;
    const int j0 = blockIdx.x * 8;
    const int r0 = min(max(i0 - 3, 0), 50);   // 14-row window, always in-bounds
    const int c0 = min(max(j0 - 3, 0), 50);

    __shared__ float kv_s[196][33];   // 14x14 region x 32d (padded) — K then V
    __shared__ float q_s [64][33];    // 64 pixels x 32d; reused as output staging
    __shared__ float p_s [64][50];    // softmax probs per pixel
    __shared__ float rpb_s[169];

    const int tid  = threadIdx.x;
    const int lane = tid & 31;
    const int w    = tid >> 5;

    const float* qbase = qkv + (size_t)(b * 576 +       h * 32) * HW;
    const float* kbase = qkv + (size_t)(b * 576 + 192 + h * 32) * HW;
    const float* vbase = qkv + (size_t)(b * 576 + 384 + h * 32) * HW;

    // load q tile (8x8 x 32d)
    for (int e = tid; e < 2048; e += 256) {
        int d  = e >> 6;
        int pi = (e >> 3) & 7;
        int pj = e & 7;
        q_s[pi * 8 + pj][d] = qbase[(size_t)d * HW + (i0 + pi) * WID + (j0 + pj)];
    }
    // load K tile (14x14 x 32d)
    for (int e = tid; e < 6272; e += 256) {
        int d = e / 196;
        int p = e % 196;
        kv_s[p][d] = kbase[(size_t)d * HW + (r0 + p / 14) * WID + (c0 + p % 14)];
    }
    for (int e = tid; e < 169; e += 256) rpb_s[e] = rpb[h * 169 + e];
    __syncthreads();

    const int i  = i0 + w;
    const int si = min(max(i - 3, 0), 57);
    const float tscale = temp[h];

    const int n1 = lane;
    const int ki1 = n1 / 7, kj1 = n1 % 7;
    const int n2 = lane + 32;                 // valid if lane < 17
    const int ki2 = n2 / 7, kj2 = n2 % 7;
    const bool has2 = (lane < 17);

    // Phase 1: scores + softmax for this warp's 8 pixels
    for (int px = 0; px < 8; px++) {
        const int j  = j0 + px;
        const int sj = min(max(j - 3, 0), 57);
        const int base = (si - r0) * 14 + (sj - c0);
        const float* qp = q_s[w * 8 + px];
        const int o1 = base + ki1 * 14 + kj1;
        const int o2 = base + ki2 * 14 + kj2;

        float s1 = 0.f, s2 = 0.f;
#pragma unroll
        for (int d = 0; d < 32; d++) {
            float qd = qp[d];
            s1 += qd * kv_s[o1][d];
            s2 += qd * kv_s[o2][d];
        }
        s1 = (s1 + rpb_s[(si + ki1 - i + 6) * 13 + (sj + kj1 - j + 6)]) * tscale;
        s2 = has2 ? (s2 + rpb_s[(si + ki2 - i + 6) * 13 + (sj + kj2 - j + 6)]) * tscale
                  : -1e30f;

        float m = fmaxf(s1, s2);
#pragma unroll
        for (int o = 16; o > 0; o >>= 1) m = fmaxf(m, __shfl_xor_sync(0xffffffffu, m, o));
        float e1 = __expf(s1 - m);
        float e2 = has2 ? __expf(s2 - m) : 0.f;
        float sm = e1 + e2;
#pragma unroll
        for (int o = 16; o > 0; o >>= 1) sm += __shfl_xor_sync(0xffffffffu, sm, o);
        float inv = 1.f / sm;
        p_s[w * 8 + px][lane] = e1 * inv;
        if (has2) p_s[w * 8 + px][lane + 32] = e2 * inv;
    }
    __syncthreads();

    // Phase 2: overwrite kv_s with V tile
    for (int e = tid; e < 6272; e += 256) {
        int d = e / 196;
        int p = e % 196;
        kv_s[p][d] = vbase[(size_t)d * HW + (r0 + p / 14) * WID + (c0 + p % 14)];
    }
    __syncthreads();

    // Phase 3: out[d] = sum_n p_n * v_n[d]; lane = d
    for (int px = 0; px < 8; px++) {
        const int j  = j0 + px;
        const int sj = min(max(j - 3, 0), 57);
        const int base = (si - r0) * 14 + (sj - c0);
        const float* pp = p_s[w * 8 + px];
        float acc = 0.f;
#pragma unroll
        for (int n = 0; n < 49; n++) {
            acc += pp[n] * kv_s[base + (n / 7) * 14 + (n % 7)][lane];
        }
        q_s[w * 8 + px][lane] = acc;   // stage for coalesced store
    }
    __syncthreads();

    // Coalesced channel-major store
    for (int e = tid; e < 2048; e += 256) {
        int d  = e >> 6;
        int pi = (e >> 3) & 7;
        int pj = e & 7;
        outp[(size_t)(b * 192 + h * 32 + d) * HW + (i0 + pi) * WID + (j0 + pj)] =
            q_s[pi * 8 + pj][d];
    }
}

// ---------------------------------------------------------------------------
extern "C" void kernel_launch(void* const* d_in, const int* in_sizes, int n_in,
                              void* d_out, int out_size)
{
    const float* x    = (const float*)d_in[0];
    const float* W1   = (const float*)d_in[1];   // [576,192]
    const float* b1   = (const float*)d_in[2];
    const float* W2   = (const float*)d_in[3];   // [576,1,3,3]
    const float* b2   = (const float*)d_in[4];
    const float* temp = (const float*)d_in[5];   // [6]
    const float* rpb  = (const float*)d_in[6];   // [6,13,13]
    const float* Wp   = (const float*)d_in[7];   // [192,192]
    const float* bp   = (const float*)d_in[8];
    float* out = (float*)d_out;

    float *qkv1p, *qkv2p, *attp;
    cudaGetSymbolAddress((void**)&qkv1p, g_qkv1);
    cudaGetSymbolAddress((void**)&qkv2p, g_qkv2);
    cudaGetSymbolAddress((void**)&attp,  g_att);

    dim3 blk(256);

    // 1) qkv 1x1 conv: [576x192]@[192x4096] per batch
    gemm_bias_kernel<<<dim3(32, 9, 2), blk>>>(W1, x, b1, qkv1p, 576, 192, 4096);

    // 2) depthwise 3x3
    dwconv_kernel<<<2304, blk>>>(qkv1p, W2, b2, qkv2p);

    // 3) l2norm q,k (channels 0..383 in 32-groups)
    l2norm_kernel<<<384, blk>>>(qkv2p);

    // 4) neighborhood attention
    natten_kernel<<<dim3(8, 8, 12), blk>>>(qkv2p, rpb, temp, attp);

    // 5) projection 1x1 conv
    gemm_bias_kernel<<<dim3(32, 3, 2), blk>>>(Wp, attp, bp, out, 192, 192, 4096);
}

// round 3
// speedup vs baseline: 1.0430x; 1.0430x over previous
#include <cuda_runtime.h>
#include <math.h>

#define HW 4096
#define WID 64

// Scratch (allocation-free: device globals)
__device__ float g_qkv1[2 * 576 * 4096];   // after 1x1 conv
__device__ float g_qkv2[2 * 576 * 4096];   // after depthwise 3x3 (+ q,k normalized in place)
__device__ float g_att [2 * 192 * 4096];   // attention output (channel = h*32+d)

// ---------------------------------------------------------------------------
// GEMM with bias: C[z] = A[M,K] @ B[z][K,N] + bias  (row-major everywhere)
// BM=64 BN=128 BK=16, 256 threads, 4x8 register tile, global->reg prefetch.
// ---------------------------------------------------------------------------
__global__ void gemm_bias_kernel(const float* __restrict__ A,
                                 const float* __restrict__ Bg,
                                 const float* __restrict__ bias,
                                 float* __restrict__ Cg,
                                 int M, int K, int N)
{
    __shared__ float As[16][64];
    __shared__ float Bs[16][128];

    const int bN = blockIdx.x * 128;
    const int bM = blockIdx.y * 64;
    const float* Bp = Bg + (size_t)blockIdx.z * (size_t)K * N;
    float*       Cp = Cg + (size_t)blockIdx.z * (size_t)M * N;

    const int tid  = threadIdx.x;
    const int tcol = tid & 15;    // 16 cols * TN(8) = 128
    const int trow = tid >> 4;    // 16 rows * TM(4) = 64

    float acc[4][8];
#pragma unroll
    for (int i = 0; i < 4; i++)
#pragma unroll
        for (int j = 0; j < 8; j++) acc[i][j] = 0.f;

    const int a_r = tid >> 2;         // 0..63
    const int a_c = (tid & 3) << 2;   // 0,4,8,12
    const int b_r = tid >> 4;         // 0..15
    const int b_c = (tid & 15) << 3;  // 0..120

    const float* aptr = &A[(size_t)(bM + a_r) * K + a_c];
    const float* bptr = Bp + (size_t)b_r * N + bN + b_c;

    // prefetch tile 0
    float4 apre = *reinterpret_cast<const float4*>(aptr);
    float4 bpre0 = *reinterpret_cast<const float4*>(bptr);
    float4 bpre1 = *reinterpret_cast<const float4*>(bptr + 4);

    for (int k0 = 0; k0 < K; k0 += 16) {
        As[a_c + 0][a_r] = apre.x;
        As[a_c + 1][a_r] = apre.y;
        As[a_c + 2][a_r] = apre.z;
        As[a_c + 3][a_r] = apre.w;
        *reinterpret_cast<float4*>(&Bs[b_r][b_c])     = bpre0;
        *reinterpret_cast<float4*>(&Bs[b_r][b_c + 4]) = bpre1;
        __syncthreads();

        if (k0 + 16 < K) {  // prefetch next tile while computing this one
            apre  = *reinterpret_cast<const float4*>(aptr + k0 + 16);
            bpre0 = *reinterpret_cast<const float4*>(bptr + (size_t)(k0 + 16) * N);
            bpre1 = *reinterpret_cast<const float4*>(bptr + (size_t)(k0 + 16) * N + 4);
        }

#pragma unroll
        for (int k = 0; k < 16; k++) {
            float a4[4], b8[8];
            *reinterpret_cast<float4*>(a4)     = *reinterpret_cast<const float4*>(&As[k][trow << 2]);
            *reinterpret_cast<float4*>(b8)     = *reinterpret_cast<const float4*>(&Bs[k][tcol << 3]);
            *reinterpret_cast<float4*>(b8 + 4) = *reinterpret_cast<const float4*>(&Bs[k][(tcol << 3) + 4]);
#pragma unroll
            for (int i = 0; i < 4; i++)
#pragma unroll
                for (int j = 0; j < 8; j++)
                    acc[i][j] += a4[i] * b8[j];
        }
        __syncthreads();
    }

#pragma unroll
    for (int i = 0; i < 4; i++) {
        int gm = bM + (trow << 2) + i;
        float bv = bias[gm];
        float* dst = Cp + (size_t)gm * N + bN + (tcol << 3);
        float4 o0 = make_float4(acc[i][0] + bv, acc[i][1] + bv, acc[i][2] + bv, acc[i][3] + bv);
        float4 o1 = make_float4(acc[i][4] + bv, acc[i][5] + bv, acc[i][6] + bv, acc[i][7] + bv);
        *reinterpret_cast<float4*>(dst)     = o0;
        *reinterpret_cast<float4*>(dst + 4) = o1;
    }
}

// ---------------------------------------------------------------------------
// Depthwise 3x3 SAME conv, NCHW, 576 channels. Thread = (b, c, row, 8-col strip).
// ---------------------------------------------------------------------------
__global__ void dwconv_kernel(const float* __restrict__ in,
                              const float* __restrict__ w9,
                              const float* __restrict__ bias,
                              float* __restrict__ outp)
{
    int idx = blockIdx.x * 256 + threadIdx.x;
    if (idx >= 2 * 576 * 64 * 8) return;
    const int j0 = (idx & 7) << 3;
    const int i  = (idx >> 3) & 63;
    const int bc = idx >> 9;
    const int c  = bc % 576;

    const float* src = in + (size_t)bc * HW;

    float wv[9];
#pragma unroll
    for (int t = 0; t < 9; t++) wv[t] = __ldg(&w9[c * 9 + t]);
    const float bv = __ldg(&bias[c]);

    float a[8];
#pragma unroll
    for (int j = 0; j < 8; j++) a[j] = bv;

#pragma unroll
    for (int di = 0; di < 3; di++) {
        int ii = i + di - 1;
        if (ii < 0 || ii > 63) continue;
        float r[10];
#pragma unroll
        for (int t = 0; t < 10; t++) {
            int jj = j0 - 1 + t;
            r[t] = (jj >= 0 && jj < 64) ? src[ii * WID + jj] : 0.f;
        }
#pragma unroll
        for (int dj = 0; dj < 3; dj++) {
            float wc = wv[di * 3 + dj];
#pragma unroll
            for (int j = 0; j < 8; j++) a[j] += wc * r[j + dj];
        }
    }

    float* dst = outp + (size_t)bc * HW + i * WID + j0;
    *reinterpret_cast<float4*>(dst)     = make_float4(a[0], a[1], a[2], a[3]);
    *reinterpret_cast<float4*>(dst + 4) = make_float4(a[4], a[5], a[6], a[7]);
}

// ---------------------------------------------------------------------------
// L2-normalize q and k over hd=32.
// ---------------------------------------------------------------------------
__global__ void l2norm_kernel(float* __restrict__ t)
{
    const int gw   = (blockIdx.x * blockDim.x + threadIdx.x) >> 5;
    const int lane = threadIdx.x & 31;
    const int pg = gw & 127;
    const int hq = (gw >> 7) % 12;
    const int b  = (gw >> 7) / 12;

    float* base = t + (size_t)(b * 576 + hq * 32) * HW + pg * 32 + lane;
    float v[32];
    float ss = 0.f;
#pragma unroll
    for (int d = 0; d < 32; d++) {
        v[d] = base[(size_t)d * HW];
        ss += v[d] * v[d];
    }
    float sc = 1.f / fmaxf(sqrtf(ss), 1e-12f);
#pragma unroll
    for (int d = 0; d < 32; d++) base[(size_t)d * HW] = v[d] * sc;
}

// ---------------------------------------------------------------------------
// Neighborhood attention (7x7 clipped window), block = (8x8 pixel tile, head, b).
// Vectorized (float4) smem access. K and V phases share kv_s. q-tile, probs,
// and output staging share `buf` (row lifetime-disjoint).
//   buf row p (52 floats): [0..31]=q[p][d] -> overwritten by probs [0..48]
//                          -> overwritten by out[p][d] [0..31]
// ---------------------------------------------------------------------------
#define KVS 36   // padded row stride for kv tile (16B aligned)
#define BFS 52   // padded row stride for buf (16B aligned)

__global__ void natten_kernel(const float* __restrict__ qkv,
                              const float* __restrict__ rpb,
                              const float* __restrict__ temp,
                              float* __restrict__ outp)
{
    const int h  = blockIdx.z % 6;
    const int b  = blockIdx.z / 6;
    const int i0 = blockIdx.y * 8;
    const int j0 = blockIdx.x * 8;
    const int r0 = min(max(i0 - 3, 0), 50);
    const int c0 = min(max(j0 - 3, 0), 50);

    __shared__ alignas(16) float kv_s[196 * KVS];  // 14x14 x 32d (K then V)
    __shared__ alignas(16) float buf [64 * BFS];   // q / probs / out staging
    __shared__ float rpb_s[169];

    const int tid  = threadIdx.x;
    const int lane = tid & 31;
    const int w    = tid >> 5;

    const float* qbase = qkv + (size_t)(b * 576 +       h * 32) * HW;
    const float* kbase = qkv + (size_t)(b * 576 + 192 + h * 32) * HW;
    const float* vbase = qkv + (size_t)(b * 576 + 384 + h * 32) * HW;

    // load q tile (8x8 x 32d) into buf[p][0..31]
    for (int e = tid; e < 2048; e += 256) {
        int d  = e >> 6;
        int pi = (e >> 3) & 7;
        int pj = e & 7;
        buf[(pi * 8 + pj) * BFS + d] = qbase[(size_t)d * HW + (i0 + pi) * WID + (j0 + pj)];
    }
    // load K tile (14x14 x 32d)
    for (int e = tid; e < 6272; e += 256) {
        int d = e / 196;
        int p = e % 196;
        kv_s[p * KVS + d] = kbase[(size_t)d * HW + (r0 + p / 14) * WID + (c0 + p % 14)];
    }
    for (int e = tid; e < 169; e += 256) rpb_s[e] = rpb[h * 169 + e];
    __syncthreads();

    const int i  = i0 + w;
    const int si = min(max(i - 3, 0), 57);
    const float tscale = temp[h];

    const int n1 = lane;
    const int ki1 = n1 / 7, kj1 = n1 % 7;
    const int n2 = lane + 32;
    const int ki2 = n2 / 7, kj2 = n2 % 7;
    const bool has2 = (lane < 17);

    // ---- Phase 1: scores + softmax (lane = neighbor, float4 over d) ----
#pragma unroll
    for (int px = 0; px < 8; px++) {
        const int j  = j0 + px;
        const int sj = min(max(j - 3, 0), 57);
        const int base = (si - r0) * 14 + (sj - c0);
        const int o1 = base + ki1 * 14 + kj1;
        const int o2 = has2 ? (base + ki2 * 14 + kj2) : 0;

        const float4* qp = reinterpret_cast<const float4*>(&buf[(w * 8 + px) * BFS]);
        const float4* k1 = reinterpret_cast<const float4*>(&kv_s[o1 * KVS]);
        const float4* k2 = reinterpret_cast<const float4*>(&kv_s[o2 * KVS]);

        float s1 = 0.f, s2 = 0.f;
#pragma unroll
        for (int kd = 0; kd < 8; kd++) {
            float4 q4 = qp[kd];
            float4 a  = k1[kd];
            float4 c  = k2[kd];
            s1 += q4.x * a.x + q4.y * a.y + q4.z * a.z + q4.w * a.w;
            s2 += q4.x * c.x + q4.y * c.y + q4.z * c.z + q4.w * c.w;
        }
        const int b1i = (si + ki1 - i + 6) * 13 + (sj + kj1 - j + 6);
        const int b2i = has2 ? (si + ki2 - i + 6) * 13 + (sj + kj2 - j + 6) : 0;
        s1 = (s1 + rpb_s[b1i]) * tscale;
        s2 = has2 ? (s2 + rpb_s[b2i]) * tscale : -1e30f;

        float m = fmaxf(s1, s2);
#pragma unroll
        for (int o = 16; o > 0; o >>= 1) m = fmaxf(m, __shfl_xor_sync(0xffffffffu, m, o));
        float e1 = __expf(s1 - m);
        float e2 = has2 ? __expf(s2 - m) : 0.f;
        float sm = e1 + e2;
#pragma unroll
        for (int o = 16; o > 0; o >>= 1) sm += __shfl_xor_sync(0xffffffffu, sm, o);
        float inv = 1.f / sm;
        // q row for this px is dead now: overwrite with probs
        buf[(w * 8 + px) * BFS + n1] = e1 * inv;
        if (has2) buf[(w * 8 + px) * BFS + n2] = e2 * inv;
    }
    __syncthreads();

    // ---- Phase 2: overwrite kv_s with V tile ----
    for (int e = tid; e < 6272; e += 256) {
        int d = e / 196;
        int p = e % 196;
        kv_s[p * KVS + d] = vbase[(size_t)d * HW + (r0 + p / 14) * WID + (c0 + p % 14)];
    }
    __syncthreads();

    // ---- Phase 3: out[d] = sum_n p_n * v_n[d]. 8 lanes per pixel, float4 acc ----
    {
        const int oct = lane >> 3;   // 0..3 : pixel within group of 4
        const int dl  = lane & 7;    // d-quarter index
#pragma unroll
        for (int pass = 0; pass < 2; pass++) {
            const int px = pass * 4 + oct;
            const int j  = j0 + px;
            const int sj = min(max(j - 3, 0), 57);
            const int base = (si - r0) * 14 + (sj - c0);
            const float* pp = &buf[(w * 8 + px) * BFS];

            float4 acc = make_float4(0.f, 0.f, 0.f, 0.f);
#pragma unroll
            for (int n = 0; n < 49; n++) {
                const int row = base + (n / 7) * 14 + (n % 7);
                float p = pp[n];
                float4 v4 = reinterpret_cast<const float4*>(&kv_s[row * KVS])[dl];
                acc.x += p * v4.x;
                acc.y += p * v4.y;
                acc.z += p * v4.z;
                acc.w += p * v4.w;
            }
            // probs row for this px fully consumed: stage output in place
            reinterpret_cast<float4*>(&buf[(w * 8 + px) * BFS])[dl] = acc;
        }
    }
    __syncthreads();

    // ---- Coalesced channel-major store ----
    for (int e = tid; e < 2048; e += 256) {
        int d  = e >> 6;
        int pi = (e >> 3) & 7;
        int pj = e & 7;
        outp[(size_t)(b * 192 + h * 32 + d) * HW + (i0 + pi) * WID + (j0 + pj)] =
            buf[(pi * 8 + pj) * BFS + d];
    }
}

// ---------------------------------------------------------------------------
extern "C" void kernel_launch(void* const* d_in, const int* in_sizes, int n_in,
                              void* d_out, int out_size)
{
    const float* x    = (const float*)d_in[0];
    const float* W1   = (const float*)d_in[1];
    const float* b1   = (const float*)d_in[2];
    const float* W2   = (const float*)d_in[3];
    const float* b2   = (const float*)d_in[4];
    const float* temp = (const float*)d_in[5];
    const float* rpb  = (const float*)d_in[6];
    const float* Wp   = (const float*)d_in[7];
    const float* bp   = (const float*)d_in[8];
    float* out = (float*)d_out;

    float *qkv1p, *qkv2p, *attp;
    cudaGetSymbolAddress((void**)&qkv1p, g_qkv1);
    cudaGetSymbolAddress((void**)&qkv2p, g_qkv2);
    cudaGetSymbolAddress((void**)&attp,  g_att);

    dim3 blk(256);

    // 1) qkv 1x1 conv: [576x192]@[192x4096] per batch
    gemm_bias_kernel<<<dim3(32, 9, 2), blk>>>(W1, x, b1, qkv1p, 576, 192, 4096);

    // 2) depthwise 3x3
    dwconv_kernel<<<2304, blk>>>(qkv1p, W2, b2, qkv2p);

    // 3) l2norm q,k
    l2norm_kernel<<<384, blk>>>(qkv2p);

    // 4) neighborhood attention
    natten_kernel<<<dim3(8, 8, 12), blk>>>(qkv2p, rpb, temp, attp);

    // 5) projection 1x1 conv
    gemm_bias_kernel<<<dim3(32, 3, 2), blk>>>(Wp, attp, bp, out, 192, 192, 4096);
}

// round 7
// speedup vs baseline: 1.0550x; 1.0115x over previous
#include <cuda_runtime.h>
#include <math.h>

#define HW 4096
#define WID 64

// Scratch (allocation-free: device globals)
__device__ float g_qkv1[2 * 576 * 4096];   // after 1x1 conv
__device__ float g_qkv2[2 * 576 * 4096];   // after depthwise 3x3 (raw q,k,v — norm fused in natten)
__device__ float g_att [2 * 192 * 4096];   // attention output (channel = h*32+d)

// ---------------------------------------------------------------------------
// GEMM with bias: C[z] = A[M,K] @ B[z][K,N] + bias  (row-major everywhere)
// BM=64 BN=128 BK=16, 256 threads, 4x8 register tile, global->reg prefetch.
// ---------------------------------------------------------------------------
__global__ void gemm_bias_kernel(const float* __restrict__ A,
                                 const float* __restrict__ Bg,
                                 const float* __restrict__ bias,
                                 float* __restrict__ Cg,
                                 int M, int K, int N)
{
    __shared__ float As[16][64];
    __shared__ float Bs[16][128];

    const int bN = blockIdx.x * 128;
    const int bM = blockIdx.y * 64;
    const float* Bp = Bg + (size_t)blockIdx.z * (size_t)K * N;
    float*       Cp = Cg + (size_t)blockIdx.z * (size_t)M * N;

    const int tid  = threadIdx.x;
    const int tcol = tid & 15;
    const int trow = tid >> 4;

    float acc[4][8];
#pragma unroll
    for (int i = 0; i < 4; i++)
#pragma unroll
        for (int j = 0; j < 8; j++) acc[i][j] = 0.f;

    const int a_r = tid >> 2;
    const int a_c = (tid & 3) << 2;
    const int b_r = tid >> 4;
    const int b_c = (tid & 15) << 3;

    const float* aptr = &A[(size_t)(bM + a_r) * K + a_c];
    const float* bptr = Bp + (size_t)b_r * N + bN + b_c;

    float4 apre = *reinterpret_cast<const float4*>(aptr);
    float4 bpre0 = *reinterpret_cast<const float4*>(bptr);
    float4 bpre1 = *reinterpret_cast<const float4*>(bptr + 4);

    for (int k0 = 0; k0 < K; k0 += 16) {
        As[a_c + 0][a_r] = apre.x;
        As[a_c + 1][a_r] = apre.y;
        As[a_c + 2][a_r] = apre.z;
        As[a_c + 3][a_r] = apre.w;
        *reinterpret_cast<float4*>(&Bs[b_r][b_c])     = bpre0;
        *reinterpret_cast<float4*>(&Bs[b_r][b_c + 4]) = bpre1;
        __syncthreads();

        if (k0 + 16 < K) {
            apre  = *reinterpret_cast<const float4*>(aptr + k0 + 16);
            bpre0 = *reinterpret_cast<const float4*>(bptr + (size_t)(k0 + 16) * N);
            bpre1 = *reinterpret_cast<const float4*>(bptr + (size_t)(k0 + 16) * N + 4);
        }

#pragma unroll
        for (int k = 0; k < 16; k++) {
            float a4[4], b8[8];
            *reinterpret_cast<float4*>(a4)     = *reinterpret_cast<const float4*>(&As[k][trow << 2]);
            *reinterpret_cast<float4*>(b8)     = *reinterpret_cast<const float4*>(&Bs[k][tcol << 3]);
            *reinterpret_cast<float4*>(b8 + 4) = *reinterpret_cast<const float4*>(&Bs[k][(tcol << 3) + 4]);
#pragma unroll
            for (int i = 0; i < 4; i++)
#pragma unroll
                for (int j = 0; j < 8; j++)
                    acc[i][j] += a4[i] * b8[j];
        }
        __syncthreads();
    }

#pragma unroll
    for (int i = 0; i < 4; i++) {
        int gm = bM + (trow << 2) + i;
        float bv = bias[gm];
        float* dst = Cp + (size_t)gm * N + bN + (tcol << 3);
        float4 o0 = make_float4(acc[i][0] + bv, acc[i][1] + bv, acc[i][2] + bv, acc[i][3] + bv);
        float4 o1 = make_float4(acc[i][4] + bv, acc[i][5] + bv, acc[i][6] + bv, acc[i][7] + bv);
        *reinterpret_cast<float4*>(dst)     = o0;
        *reinterpret_cast<float4*>(dst + 4) = o1;
    }
}

// ---------------------------------------------------------------------------
// Depthwise 3x3 SAME conv, NCHW, 576 channels.
// ---------------------------------------------------------------------------
__global__ void dwconv_kernel(const float* __restrict__ in,
                              const float* __restrict__ w9,
                              const float* __restrict__ bias,
                              float* __restrict__ outp)
{
    int idx = blockIdx.x * 256 + threadIdx.x;
    if (idx >= 2 * 576 * 64 * 8) return;
    const int j0 = (idx & 7) << 3;
    const int i  = (idx >> 3) & 63;
    const int bc = idx >> 9;
    const int c  = bc % 576;

    const float* src = in + (size_t)bc * HW;

    float wv[9];
#pragma unroll
    for (int t = 0; t < 9; t++) wv[t] = __ldg(&w9[c * 9 + t]);
    const float bv = __ldg(&bias[c]);

    float a[8];
#pragma unroll
    for (int j = 0; j < 8; j++) a[j] = bv;

#pragma unroll
    for (int di = 0; di < 3; di++) {
        int ii = i + di - 1;
        if (ii < 0 || ii > 63) continue;
        float r[10];
#pragma unroll
        for (int t = 0; t < 10; t++) {
            int jj = j0 - 1 + t;
            r[t] = (jj >= 0 && jj < 64) ? src[ii * WID + jj] : 0.f;
        }
#pragma unroll
        for (int dj = 0; dj < 3; dj++) {
            float wc = wv[di * 3 + dj];
#pragma unroll
            for (int j = 0; j < 8; j++) a[j] += wc * r[j + dj];
        }
    }

    float* dst = outp + (size_t)bc * HW + i * WID + j0;
    *reinterpret_cast<float4*>(dst)     = make_float4(a[0], a[1], a[2], a[3]);
    *reinterpret_cast<float4*>(dst + 4) = make_float4(a[4], a[5], a[6], a[7]);
}

// ---------------------------------------------------------------------------
// Neighborhood attention (7x7 clipped window), block = (8x8 pixel tile, head, b).
// L2-norm of q and K fused here (applied to the smem tiles after load).
// __launch_bounds__(256,5) -> 5 blocks/SM -> ~1.0 wave over 768 blocks.
// ---------------------------------------------------------------------------
#define KVS 36   // padded row stride for kv tile (16B aligned)
#define BFS 52   // padded row stride for buf (16B aligned)

__global__ __launch_bounds__(256, 5)
void natten_kernel(const float* __restrict__ qkv,
                   const float* __restrict__ rpb,
                   const float* __restrict__ temp,
                   float* __restrict__ outp)
{
    const int h  = blockIdx.z % 6;
    const int b  = blockIdx.z / 6;
    const int i0 = blockIdx.y * 8;
    const int j0 = blockIdx.x * 8;
    const int r0 = min(max(i0 - 3, 0), 50);
    const int c0 = min(max(j0 - 3, 0), 50);

    __shared__ alignas(16) float kv_s[196 * KVS];  // 14x14 x 32d (K then V)
    __shared__ alignas(16) float buf [64 * BFS];   // q / probs / out staging
    __shared__ float rpb_s[169];

    const int tid  = threadIdx.x;
    const int lane = tid & 31;
    const int w    = tid >> 5;

    const float* qbase = qkv + (size_t)(b * 576 +       h * 32) * HW;
    const float* kbase = qkv + (size_t)(b * 576 + 192 + h * 32) * HW;
    const float* vbase = qkv + (size_t)(b * 576 + 384 + h * 32) * HW;

    // load q tile (8x8 x 32d) into buf[p][0..31]  (unnormalized)
    for (int e = tid; e < 2048; e += 256) {
        int d  = e >> 6;
        int pi = (e >> 3) & 7;
        int pj = e & 7;
        buf[(pi * 8 + pj) * BFS + d] = qbase[(size_t)d * HW + (i0 + pi) * WID + (j0 + pj)];
    }
    // load K tile (14x14 x 32d) (unnormalized)
    for (int e = tid; e < 6272; e += 256) {
        int d = e / 196;
        int p = e % 196;
        kv_s[p * KVS + d] = kbase[(size_t)d * HW + (r0 + p / 14) * WID + (c0 + p % 14)];
    }
    for (int e = tid; e < 169; e += 256) rpb_s[e] = rpb[h * 169 + e];
    __syncthreads();

    // ---- Fused L2-norm: K rows (196) and q rows (64).
    //      Threads 0..195 handle K rows; threads 0..63 ALSO handle q rows. ----
    if (tid < 196) {
        float4* r = reinterpret_cast<float4*>(&kv_s[tid * KVS]);
        float ss = 0.f;
#pragma unroll
        for (int t = 0; t < 8; t++) {
            float4 v = r[t];
            ss += v.x * v.x + v.y * v.y + v.z * v.z + v.w * v.w;
        }
        float sc = 1.f / fmaxf(sqrtf(ss), 1e-12f);
#pragma unroll
        for (int t = 0; t < 8; t++) {
            float4 v = r[t];
            r[t] = make_float4(v.x * sc, v.y * sc, v.z * sc, v.w * sc);
        }
    }
    if (tid < 64) {
        float4* r = reinterpret_cast<float4*>(&buf[tid * BFS]);
        float ss = 0.f;
#pragma unroll
        for (int t = 0; t < 8; t++) {
            float4 v = r[t];
            ss += v.x * v.x + v.y * v.y + v.z * v.z + v.w * v.w;
        }
        float sc = 1.f / fmaxf(sqrtf(ss), 1e-12f);
#pragma unroll
        for (int t = 0; t < 8; t++) {
            float4 v = r[t];
            r[t] = make_float4(v.x * sc, v.y * sc, v.z * sc, v.w * sc);
        }
    }
    __syncthreads();

    const int i  = i0 + w;
    const int si = min(max(i - 3, 0), 57);
    const float tscale = temp[h];

    const int ki1 = lane / 7, kj1 = lane % 7;
    const int ki2 = (lane + 32) / 7, kj2 = (lane + 32) % 7;
    const bool has2 = (lane < 17);

    // hoisted lane constants
    const int rowBase = (si - r0) * 14;
    const int riOff   = si - i + 6;                   // per-warp
    const int kOff1 = ki1 * 14 + kj1;
    const int kOff2 = ki2 * 14 + kj2;
    const int rb1   = (riOff + ki1) * 13 + kj1;       // bias row const
    const int rb2   = (riOff + ki2) * 13 + kj2;

    // ---- Phase 1: scores + softmax (lane = neighbor, float4 over d) ----
#pragma unroll
    for (int px = 0; px < 8; px++) {
        const int j  = j0 + px;
        const int sj = min(max(j - 3, 0), 57);
        const int base  = rowBase + (sj - c0);
        const int cjOff = sj - j + 6;
        const int o1 = base + kOff1;
        const int o2 = has2 ? (base + kOff2) : 0;

        const float4* qp = reinterpret_cast<const float4*>(&buf[(w * 8 + px) * BFS]);
        const float4* k1 = reinterpret_cast<const float4*>(&kv_s[o1 * KVS]);
        const float4* k2 = reinterpret_cast<const float4*>(&kv_s[o2 * KVS]);

        float s1 = 0.f, s2 = 0.f;
#pragma unroll
        for (int kd = 0; kd < 8; kd++) {
            float4 q4 = qp[kd];
            float4 a  = k1[kd];
            float4 c  = k2[kd];
            s1 += q4.x * a.x + q4.y * a.y + q4.z * a.z + q4.w * a.w;
            s2 += q4.x * c.x + q4.y * c.y + q4.z * c.z + q4.w * c.w;
        }
        s1 = (s1 + rpb_s[rb1 + cjOff]) * tscale;
        s2 = has2 ? (s2 + rpb_s[rb2 + cjOff]) * tscale : -1e30f;

        float m = fmaxf(s1, s2);
#pragma unroll
        for (int o = 16; o > 0; o >>= 1) m = fmaxf(m, __shfl_xor_sync(0xffffffffu, m, o));
        float e1 = __expf(s1 - m);
        float e2 = has2 ? __expf(s2 - m) : 0.f;
        float sm = e1 + e2;
#pragma unroll
        for (int o = 16; o > 0; o >>= 1) sm += __shfl_xor_sync(0xffffffffu, sm, o);
        float inv = 1.f / sm;
        // q row for this px is dead now: overwrite with probs
        buf[(w * 8 + px) * BFS + lane] = e1 * inv;
        if (has2) buf[(w * 8 + px) * BFS + lane + 32] = e2 * inv;
    }
    __syncthreads();

    // ---- Phase 2: overwrite kv_s with V tile (NOT normalized) ----
    for (int e = tid; e < 6272; e += 256) {
        int d = e / 196;
        int p = e % 196;
        kv_s[p * KVS + d] = vbase[(size_t)d * HW + (r0 + p / 14) * WID + (c0 + p % 14)];
    }
    __syncthreads();

    // ---- Phase 3: out[d] = sum_n p_n * v_n[d]. 8 lanes per pixel, float4 acc ----
    {
        const int oct = lane >> 3;
        const int dl  = lane & 7;
#pragma unroll
        for (int pass = 0; pass < 2; pass++) {
            const int px = pass * 4 + oct;
            const int j  = j0 + px;
            const int sj = min(max(j - 3, 0), 57);
            const int base = rowBase + (sj - c0);
            const float* pp = &buf[(w * 8 + px) * BFS];

            float4 acc = make_float4(0.f, 0.f, 0.f, 0.f);
            const float* vrow = &kv_s[base * KVS];
            int n = 0;
#pragma unroll
            for (int ki = 0; ki < 7; ki++) {
#pragma unroll
                for (int kj = 0; kj < 7; kj++) {
                    float p = pp[n++];
                    float4 v4 = reinterpret_cast<const float4*>(vrow + kj * KVS)[dl];
                    acc.x += p * v4.x;
                    acc.y += p * v4.y;
                    acc.z += p * v4.z;
                    acc.w += p * v4.w;
                }
                vrow += 14 * KVS;
            }
            reinterpret_cast<float4*>(&buf[(w * 8 + px) * BFS])[dl] = acc;
        }
    }
    __syncthreads();

    // ---- Coalesced channel-major store ----
    for (int e = tid; e < 2048; e += 256) {
        int d  = e >> 6;
        int pi = (e >> 3) & 7;
        int pj = e & 7;
        outp[(size_t)(b * 192 + h * 32 + d) * HW + (i0 + pi) * WID + (j0 + pj)] =
            buf[(pi * 8 + pj) * BFS + d];
    }
}

// ---------------------------------------------------------------------------
extern "C" void kernel_launch(void* const* d_in, const int* in_sizes, int n_in,
                              void* d_out, int out_size)
{
    const float* x    = (const float*)d_in[0];
    const float* W1   = (const float*)d_in[1];
    const float* b1   = (const float*)d_in[2];
    const float* W2   = (const float*)d_in[3];
    const float* b2   = (const float*)d_in[4];
    const float* temp = (const float*)d_in[5];
    const float* rpb  = (const float*)d_in[6];
    const float* Wp   = (const float*)d_in[7];
    const float* bp   = (const float*)d_in[8];
    float* out = (float*)d_out;

    float *qkv1p, *qkv2p, *attp;
    cudaGetSymbolAddress((void**)&qkv1p, g_qkv1);
    cudaGetSymbolAddress((void**)&qkv2p, g_qkv2);
    cudaGetSymbolAddress((void**)&attp,  g_att);

    dim3 blk(256);

    // 1) qkv 1x1 conv: [576x192]@[192x4096] per batch
    gemm_bias_kernel<<<dim3(32, 9, 2), blk>>>(W1, x, b1, qkv1p, 576, 192, 4096);

    // 2) depthwise 3x3
    dwconv_kernel<<<2304, blk>>>(qkv1p, W2, b2, qkv2p);

    // 3) neighborhood attention (l2norm fused)
    natten_kernel<<<dim3(8, 8, 12), blk>>>(qkv2p, rpb, temp, attp);

    // 4) projection 1x1 conv
    gemm_bias_kernel<<<dim3(32, 3, 2), blk>>>(Wp, attp, bp, out, 192, 192, 4096);
}